// round 11
// baseline (speedup 1.0000x reference)
#include <cuda_runtime.h>
#include <math_constants.h>

// Shapes (fixed by problem)
#define B 32
#define T 512
#define D 512
#define H 8
#define S 196
#define LAYER_ID 2
#define K_TOP 51   // int(0.1 * 512)
#define NBLK 16    // blocks per batch
#define CHUNK 32   // t's per block
#define NG 32      // partial groups (NBLK x 2 subgroups)

// Scratch (allocation-free rule: __device__ globals; zero-initialized)
__device__ float g_w[B * T];
__device__ float g_part[B][NG][S];
__device__ int   g_sync[B];

// ---------------------------------------------------------------------------
// Kernel 1: cosine weights. One warp handles TWO t-rows (12 LDG.128/thread),
// no smem, no syncthreads. grid (T/16, B), 256 threads.  [validated R6]
// ---------------------------------------------------------------------------
__global__ __launch_bounds__(256) void k_weights(
    const float* __restrict__ fore,     // (B, D)
    const float* __restrict__ embed,    // (B, T, D)
    const int*   __restrict__ targets)  // (B, T+1) int32
{
    const int b    = blockIdx.y;
    const int lane = threadIdx.x & 31;
    const int warp = threadIdx.x >> 5;
    const int t0   = (blockIdx.x * 8 + warp) * 2;

    const float4* yrow = reinterpret_cast<const float4*>(fore + (size_t)b * D);
    const float4* x0   = reinterpret_cast<const float4*>(embed + ((size_t)b * T + t0) * D);
    const float4* x1   = x0 + D / 4;

    float4 yv[4], xa[4], xb[4];
#pragma unroll
    for (int i = 0; i < 4; i++) {
        yv[i] = __ldg(&yrow[lane + i * 32]);
        xa[i] = __ldg(&x0[lane + i * 32]);
        xb[i] = __ldg(&x1[lane + i * 32]);
    }

    float n0 = 0.f, n1 = 0.f, xs0 = 0.f, xs1 = 0.f, ys = 0.f;
#pragma unroll
    for (int i = 0; i < 4; i++) {
        float4 y = yv[i], a = xa[i], c = xb[i];
        ys  += y.x * y.x + y.y * y.y + y.z * y.z + y.w * y.w;
        n0  += a.x * y.x + a.y * y.y + a.z * y.z + a.w * y.w;
        xs0 += a.x * a.x + a.y * a.y + a.z * a.z + a.w * a.w;
        n1  += c.x * y.x + c.y * y.y + c.z * y.z + c.w * y.w;
        xs1 += c.x * c.x + c.y * c.y + c.z * c.z + c.w * c.w;
    }
#pragma unroll
    for (int o = 16; o; o >>= 1) {
        n0  += __shfl_xor_sync(0xffffffffu, n0,  o);
        n1  += __shfl_xor_sync(0xffffffffu, n1,  o);
        xs0 += __shfl_xor_sync(0xffffffffu, xs0, o);
        xs1 += __shfl_xor_sync(0xffffffffu, xs1, o);
        ys  += __shfl_xor_sync(0xffffffffu, ys,  o);
    }
    if (lane < 2) {
        const int t = t0 + lane;
        float num = lane ? n1 : n0;
        float xn2 = lane ? xs1 : xs0;
        float xn  = fmaxf(sqrtf(xn2), 1e-8f);
        float yn  = fmaxf(sqrtf(ys),  1e-8f);
        float w   = num / (xn * yn);
        int tv    = targets[b * (T + 1) + t];
        bool msk  = (t == 0) || (tv > 0);
        g_w[b * T + t] = msk ? w : -1.0f;
    }
}

// ---------------------------------------------------------------------------
// Kernel 2 (fused, PDL secondary): grid (NBLK, B), 512 threads.
// Prologue (targets, m, init) overlaps k_weights; cudaGridDependency-
// Synchronize() gates the g_w read. Rank counting on 32-bit keys with
// static index tie-break, LDS.128 broadcast reads (warp-owned slice).
// ---------------------------------------------------------------------------
__global__ __launch_bounds__(512) void k_fused(
    const int*   __restrict__ targets,  // (B, T+1) int32
    const float* __restrict__ attns,    // (L, B, H, T, S)
    float*       __restrict__ out)      // (B, S)
{
    __shared__ unsigned keys[T];             // 2 KB (mapped uint32)
    __shared__ float    wvals[T];            // 2 KB (raw weights)
    __shared__ int      rank[CHUNK];
    __shared__ int      sl[CHUNK];
    __shared__ float    slw[CHUNK];
    __shared__ int      s_last;
    __shared__ float    wmin[8], wmax[8];
    __shared__ float    s_mn, s_mx;

    const int c    = blockIdx.x;   // 0..NBLK-1
    const int b    = blockIdx.y;
    const int tid  = threadIdx.x;  // 0..511
    const int lane = tid & 31;
    const int warp = tid >> 5;

    // ---- Prologue (independent of k_weights): m + init
    if (tid < CHUNK) rank[tid] = 0;
    int tv  = targets[b * (T + 1) + tid];
    int cnt = __syncthreads_count((tid == 0) || (tv > 0));
    int m   = (int)ceilf((float)cnt * 0.1f);
    m = m < K_TOP ? m : K_TOP;

    // ---- Wait for k_weights' g_w to be visible
    cudaGridDependencySynchronize();

    // ---- Phase 1: load weights, build 32-bit keys
    float w = g_w[b * T + tid];
    unsigned uf = __float_as_uint(w);
    uf = (uf & 0x80000000u) ? ~uf : (uf | 0x80000000u);   // order-preserving
    keys[tid]  = uf;
    wvals[tid] = w;
    __syncthreads();

    // ---- Phase 2: chunk-local rank. lane = t_local, warp = 32-key slice;
    // all lanes of a warp read the SAME uint4 (broadcast, conflict-free).
    // Predecessor test: (k > mk) || (k == mk && gidx < myt)  [jax stability]
    {
        const int tl  = lane;
        const int myt = c * CHUNK + tl;
        const unsigned mk = keys[myt];
        const uint4* kp = reinterpret_cast<const uint4*>(keys + warp * 32);
        int r = 0;
#pragma unroll
        for (int i = 0; i < 8; i++) {
            uint4 kv = kp[i];
            const int gb = warp * 32 + i * 4;
            r += (kv.x > mk) || ((kv.x == mk) && (gb + 0 < myt));
            r += (kv.y > mk) || ((kv.y == mk) && (gb + 1 < myt));
            r += (kv.z > mk) || ((kv.z == mk) && (gb + 2 < myt));
            r += (kv.w > mk) || ((kv.w == mk) && (gb + 3 < myt));
        }
        atomicAdd(&rank[tl], r);       // 32 spread addrs per warp
    }
    __syncthreads();

    // ---- Phase 3: selected list for this chunk, t-order (deterministic)
    bool selme = (tid < CHUNK) && (rank[tid] < m);
    if (selme) {
        int pos = 0;
#pragma unroll
        for (int i = 0; i < CHUNK; i++) pos += (i < tid) && (rank[i] < m);
        sl[pos]  = tid;
        slw[pos] = wvals[c * CHUNK + tid];
    }
    int ns = __syncthreads_count(selme);

    // ---- Phase 4: gather selected rows, 2 s-subgroups
    const int jsub = tid / S;          // 0,1 active; tid >= 392 idle
    const int s    = tid - jsub * S;
    if (jsub < 2) {
        const float* base = attns + ((size_t)(LAYER_ID * B + b)) * H * T * S + s;
        float acc = 0.f;
        for (int i = jsub; i < ns; i += 4) {   // handles i and i+2 per iter
            int i2 = i + 2;
            bool a2 = (i2 < ns);
            int   t0i = c * CHUNK + sl[i];
            int   t1i = a2 ? (c * CHUNK + sl[i2]) : t0i;
            float w0  = slw[i];
            float w1  = a2 ? slw[i2] : 0.f;
            const float* p0 = base + (size_t)t0i * S;
            const float* p1 = base + (size_t)t1i * S;
            float v0[8], v1[8];
#pragma unroll
            for (int h = 0; h < H; h++) {
                v0[h] = __ldg(p0 + (size_t)h * T * S);
                v1[h] = __ldg(p1 + (size_t)h * T * S);
            }
            float h0 = 0.f, h1 = 0.f;
#pragma unroll
            for (int h = 0; h < H; h++) { h0 += v0[h]; h1 += v1[h]; }
            acc += fmaxf(w0 * (h0 * 0.125f), 0.f);
            if (a2) acc += fmaxf(w1 * (h1 * 0.125f), 0.f);
        }
        g_part[b][c * 2 + jsub][s] = acc;
    }

    // ---- Phase 5: arrival; last block per b merges + normalizes
    __threadfence();
    __syncthreads();
    if (tid == 0) {
        int done = atomicAdd(&g_sync[b], 1);
        s_last = (done == NBLK - 1);
    }
    __syncthreads();
    if (!s_last) return;
    if (tid == 0) g_sync[b] = 0;       // reset for next graph replay
    __threadfence();

    float acc = 0.f;
    const bool active = (tid < S);
    if (active) {
#pragma unroll
        for (int g2 = 0; g2 < NG; g2++) acc += g_part[b][g2][tid];
        acc /= (float)m;
    }

    // warp-shuffle min/max over s (256 participating threads, 2 barriers)
    if (tid < 256) {
        float mn = active ? acc :  CUDART_INF_F;
        float mx = active ? acc : -CUDART_INF_F;
#pragma unroll
        for (int o = 16; o; o >>= 1) {
            mn = fminf(mn, __shfl_xor_sync(0xffffffffu, mn, o));
            mx = fmaxf(mx, __shfl_xor_sync(0xffffffffu, mx, o));
        }
        if (lane == 0) { wmin[warp] = mn; wmax[warp] = mx; }
    }
    __syncthreads();
    if (tid < 32) {
        float mn = (tid < 8) ? wmin[tid] :  CUDART_INF_F;
        float mx = (tid < 8) ? wmax[tid] : -CUDART_INF_F;
#pragma unroll
        for (int o = 4; o; o >>= 1) {
            mn = fminf(mn, __shfl_xor_sync(0xffffffffu, mn, o));
            mx = fmaxf(mx, __shfl_xor_sync(0xffffffffu, mx, o));
        }
        if (tid == 0) { s_mn = mn; s_mx = mx; }
    }
    __syncthreads();

    if (active)
        out[b * S + tid] = (acc - s_mn) / fmaxf(s_mx - s_mn, 1e-12f);
}

// ---------------------------------------------------------------------------
extern "C" void kernel_launch(void* const* d_in, const int* in_sizes, int n_in,
                              void* d_out, int out_size)
{
    const float* fore    = (const float*)d_in[0];  // (B, D)
    const float* embed   = (const float*)d_in[1];  // (B, T, D)
    const float* attns   = (const float*)d_in[2];  // (L, B, H, T, S)
    const int*   targets = (const int*)  d_in[3];  // (B, T+1) int32
    float* out = (float*)d_out;

    k_weights<<<dim3(T / 16, B), 256>>>(fore, embed, targets);

    // PDL secondary: prologue overlaps k_weights; gridsync gates g_w read.
    cudaLaunchConfig_t cfg = {};
    cfg.gridDim  = dim3(NBLK, B);
    cfg.blockDim = dim3(512);
    cfg.stream   = 0;
    cudaLaunchAttribute at[1];
    at[0].id = cudaLaunchAttributeProgrammaticStreamSerialization;
    at[0].val.programmaticStreamSerializationAllowed = 1;
    cfg.attrs = at;
    cfg.numAttrs = 1;
    cudaLaunchKernelEx(&cfg, k_fused, targets, attns, (float*)out);
}

// round 13
// speedup vs baseline: 1.2404x; 1.2404x over previous
#include <cuda_runtime.h>
#include <math_constants.h>

// Shapes (fixed by problem)
#define B 32
#define T 512
#define D 512
#define H 8
#define S 196
#define LAYER_ID 2
#define K_TOP 51   // int(0.1 * 512)
#define NBLK 16    // blocks per batch
#define CHUNK 32   // t's per block
#define NG 32      // partial groups (NBLK x 2 subgroups)

// Scratch (allocation-free rule: __device__ globals; zero-initialized)
__device__ float g_w[B * T];
__device__ float g_part[B][NG][S];
__device__ int   g_sync[B];

// ---------------------------------------------------------------------------
// Kernel 1: cosine weights. One warp handles TWO t-rows (12 LDG.128/thread),
// no smem, no syncthreads. grid (T/16, B), 256 threads.  [validated R6/R9]
// ---------------------------------------------------------------------------
__global__ __launch_bounds__(256) void k_weights(
    const float* __restrict__ fore,     // (B, D)
    const float* __restrict__ embed,    // (B, T, D)
    const int*   __restrict__ targets)  // (B, T+1) int32
{
    const int b    = blockIdx.y;
    const int lane = threadIdx.x & 31;
    const int warp = threadIdx.x >> 5;
    const int t0   = (blockIdx.x * 8 + warp) * 2;

    const float4* yrow = reinterpret_cast<const float4*>(fore + (size_t)b * D);
    const float4* x0   = reinterpret_cast<const float4*>(embed + ((size_t)b * T + t0) * D);
    const float4* x1   = x0 + D / 4;

    float4 yv[4], xa[4], xb[4];
#pragma unroll
    for (int i = 0; i < 4; i++) {
        yv[i] = __ldg(&yrow[lane + i * 32]);
        xa[i] = __ldg(&x0[lane + i * 32]);
        xb[i] = __ldg(&x1[lane + i * 32]);
    }

    float n0 = 0.f, n1 = 0.f, xs0 = 0.f, xs1 = 0.f, ys = 0.f;
#pragma unroll
    for (int i = 0; i < 4; i++) {
        float4 y = yv[i], a = xa[i], c = xb[i];
        ys  += y.x * y.x + y.y * y.y + y.z * y.z + y.w * y.w;
        n0  += a.x * y.x + a.y * y.y + a.z * y.z + a.w * y.w;
        xs0 += a.x * a.x + a.y * a.y + a.z * a.z + a.w * a.w;
        n1  += c.x * y.x + c.y * y.y + c.z * y.z + c.w * y.w;
        xs1 += c.x * c.x + c.y * c.y + c.z * c.z + c.w * c.w;
    }
#pragma unroll
    for (int o = 16; o; o >>= 1) {
        n0  += __shfl_xor_sync(0xffffffffu, n0,  o);
        n1  += __shfl_xor_sync(0xffffffffu, n1,  o);
        xs0 += __shfl_xor_sync(0xffffffffu, xs0, o);
        xs1 += __shfl_xor_sync(0xffffffffu, xs1, o);
        ys  += __shfl_xor_sync(0xffffffffu, ys,  o);
    }
    if (lane < 2) {
        const int t = t0 + lane;
        float num = lane ? n1 : n0;
        float xn2 = lane ? xs1 : xs0;
        float xn  = fmaxf(sqrtf(xn2), 1e-8f);
        float yn  = fmaxf(sqrtf(ys),  1e-8f);
        float w   = num / (xn * yn);
        int tv    = targets[b * (T + 1) + t];
        bool msk  = (t == 0) || (tv > 0);
        g_w[b * T + t] = msk ? w : -1.0f;
    }
}

// ---------------------------------------------------------------------------
// Kernel 2 (fused): grid (NBLK, B), 512 threads. 32-bit key ranking with
// static index tie-break (warp-owned slice, LDS.128 broadcast). Gather with
// 4-row x 8-head predicated batches -> 32 loads in flight per iteration.
// Last-arriving block per b merges 32 partials + normalizes (shuffle tail).
// ---------------------------------------------------------------------------
__global__ __launch_bounds__(512) void k_fused(
    const int*   __restrict__ targets,  // (B, T+1) int32
    const float* __restrict__ attns,    // (L, B, H, T, S)
    float*       __restrict__ out)      // (B, S)
{
    __shared__ unsigned keys[T];             // 2 KB (mapped uint32)
    __shared__ float    wvals[T];            // 2 KB (raw weights)
    __shared__ int      rank[CHUNK];
    __shared__ int      sl[CHUNK];
    __shared__ float    slw[CHUNK];
    __shared__ int      s_last;
    __shared__ float    wmin[8], wmax[8];
    __shared__ float    s_mn, s_mx;

    const int c    = blockIdx.x;   // 0..NBLK-1
    const int b    = blockIdx.y;
    const int tid  = threadIdx.x;  // 0..511
    const int lane = tid & 31;
    const int warp = tid >> 5;

    // ---- Phase 1: keys + m
    if (tid < CHUNK) rank[tid] = 0;
    float w = g_w[b * T + tid];
    unsigned uf = __float_as_uint(w);
    uf = (uf & 0x80000000u) ? ~uf : (uf | 0x80000000u);   // order-preserving
    keys[tid]  = uf;
    wvals[tid] = w;

    int tv  = targets[b * (T + 1) + tid];
    int cnt = __syncthreads_count((tid == 0) || (tv > 0));
    int m   = (int)ceilf((float)cnt * 0.1f);
    m = m < K_TOP ? m : K_TOP;

    // ---- Phase 2: chunk-local rank. lane = t_local, warp = 32-key slice;
    // all lanes of a warp read the SAME uint4 (broadcast, conflict-free).
    // Predecessor test: (k > mk) || (k == mk && gidx < myt)  [jax stability]
    {
        const int myt = c * CHUNK + lane;
        const unsigned mk = keys[myt];
        const uint4* kp = reinterpret_cast<const uint4*>(keys + warp * 32);
        int r = 0;
#pragma unroll
        for (int i = 0; i < 8; i++) {
            uint4 kv = kp[i];
            const int gb = warp * 32 + i * 4;
            r += (kv.x > mk) || ((kv.x == mk) && (gb + 0 < myt));
            r += (kv.y > mk) || ((kv.y == mk) && (gb + 1 < myt));
            r += (kv.z > mk) || ((kv.z == mk) && (gb + 2 < myt));
            r += (kv.w > mk) || ((kv.w == mk) && (gb + 3 < myt));
        }
        atomicAdd(&rank[lane], r);     // 32 spread addrs per warp
    }
    __syncthreads();

    // ---- Phase 3: selected list for this chunk, t-order (deterministic)
    bool selme = (tid < CHUNK) && (rank[tid] < m);
    if (selme) {
        int pos = 0;
#pragma unroll
        for (int i = 0; i < CHUNK; i++) pos += (i < tid) && (rank[i] < m);
        sl[pos]  = tid;
        slw[pos] = wvals[c * CHUNK + tid];
    }
    int ns = __syncthreads_count(selme);

    // ---- Phase 4: gather. jsub thread handles rows i = jsub, jsub+2, ...
    // 4 rows x 8 heads batched with predication -> 32 loads in flight.
    const int jsub = tid / S;          // 0,1 active; tid >= 392 idle
    const int s    = tid - jsub * S;
    if (jsub < 2) {
        const float* base = attns + ((size_t)(LAYER_ID * B + b)) * H * T * S + s;
        float acc = 0.f;
        for (int i0 = jsub; i0 < ns; i0 += 8) {      // rows i0, i0+2, i0+4, i0+6
            const float* p[4]; float wv[4];
#pragma unroll
            for (int q = 0; q < 4; q++) {
                int i  = i0 + 2 * q;
                bool a = (i < ns);
                int ii = a ? i : (ns - 1);           // safe: loop implies ns >= 1
                wv[q]  = a ? slw[ii] : 0.f;
                p[q]   = base + (size_t)(c * CHUNK + sl[ii]) * S;
            }
            float v[4][8];
#pragma unroll
            for (int q = 0; q < 4; q++)
#pragma unroll
                for (int h = 0; h < H; h++)
                    v[q][h] = __ldg(p[q] + (size_t)h * T * S);
#pragma unroll
            for (int q = 0; q < 4; q++) {
                float hs = 0.f;
#pragma unroll
                for (int h = 0; h < H; h++) hs += v[q][h];
                acc += fmaxf(wv[q] * (hs * 0.125f), 0.f);
            }
        }
        g_part[b][c * 2 + jsub][s] = acc;
    }

    // ---- Phase 5: arrival; last block per b merges + normalizes
    __threadfence();
    __syncthreads();
    if (tid == 0) {
        int done = atomicAdd(&g_sync[b], 1);
        s_last = (done == NBLK - 1);
    }
    __syncthreads();
    if (!s_last) return;
    if (tid == 0) g_sync[b] = 0;       // reset for next graph replay
    __threadfence();

    float acc = 0.f;
    const bool active = (tid < S);
    if (active) {
#pragma unroll
        for (int g2 = 0; g2 < NG; g2++) acc += g_part[b][g2][tid];
        acc /= (float)m;
    }

    // warp-shuffle min/max over s (256 participating threads, 2 barriers)
    if (tid < 256) {
        float mn = active ? acc :  CUDART_INF_F;
        float mx = active ? acc : -CUDART_INF_F;
#pragma unroll
        for (int o = 16; o; o >>= 1) {
            mn = fminf(mn, __shfl_xor_sync(0xffffffffu, mn, o));
            mx = fmaxf(mx, __shfl_xor_sync(0xffffffffu, mx, o));
        }
        if (lane == 0) { wmin[warp] = mn; wmax[warp] = mx; }
    }
    __syncthreads();
    if (tid < 32) {
        float mn = (tid < 8) ? wmin[tid] :  CUDART_INF_F;
        float mx = (tid < 8) ? wmax[tid] : -CUDART_INF_F;
#pragma unroll
        for (int o = 4; o; o >>= 1) {
            mn = fminf(mn, __shfl_xor_sync(0xffffffffu, mn, o));
            mx = fmaxf(mx, __shfl_xor_sync(0xffffffffu, mx, o));
        }
        if (tid == 0) { s_mn = mn; s_mx = mx; }
    }
    __syncthreads();

    if (active)
        out[b * S + tid] = (acc - s_mn) / fmaxf(s_mx - s_mn, 1e-12f);
}

// ---------------------------------------------------------------------------
extern "C" void kernel_launch(void* const* d_in, const int* in_sizes, int n_in,
                              void* d_out, int out_size)
{
    const float* fore    = (const float*)d_in[0];  // (B, D)
    const float* embed   = (const float*)d_in[1];  // (B, T, D)
    const float* attns   = (const float*)d_in[2];  // (L, B, H, T, S)
    const int*   targets = (const int*)  d_in[3];  // (B, T+1) int32
    float* out = (float*)d_out;

    k_weights<<<dim3(T / 16, B), 256>>>(fore, embed, targets);
    k_fused<<<dim3(NBLK, B), 512>>>(targets, attns, out);
}

// round 14
// speedup vs baseline: 1.3862x; 1.1175x over previous
#include <cuda_runtime.h>
#include <math_constants.h>

// Shapes (fixed by problem)
#define B 32
#define T 512
#define D 512
#define H 8
#define S 196
#define LAYER_ID 2
#define K_TOP 51   // int(0.1 * 512)
#define NBLK 16    // blocks per batch
#define CHUNK 32   // t's per block

// Scratch (allocation-free rule: __device__ globals; zero-initialized)
__device__ float g_w[B * T];
__device__ float g_total[B][S];
__device__ int   g_sync[B];

// ---------------------------------------------------------------------------
// Kernel 1: cosine weights (validated R6/R9) + zeroing of g_total for this
// replay (stream order guarantees it completes before k_fused's atomics).
// ---------------------------------------------------------------------------
__global__ __launch_bounds__(256) void k_weights(
    const float* __restrict__ fore,     // (B, D)
    const float* __restrict__ embed,    // (B, T, D)
    const int*   __restrict__ targets)  // (B, T+1) int32
{
    const int b    = blockIdx.y;
    const int lane = threadIdx.x & 31;
    const int warp = threadIdx.x >> 5;
    const int t0   = (blockIdx.x * 8 + warp) * 2;

    if (blockIdx.x == 0) {
        for (int i = threadIdx.x; i < S; i += 256) g_total[b][i] = 0.f;
    }

    const float4* yrow = reinterpret_cast<const float4*>(fore + (size_t)b * D);
    const float4* x0   = reinterpret_cast<const float4*>(embed + ((size_t)b * T + t0) * D);
    const float4* x1   = x0 + D / 4;

    float4 yv[4], xa[4], xb[4];
#pragma unroll
    for (int i = 0; i < 4; i++) {
        yv[i] = __ldg(&yrow[lane + i * 32]);
        xa[i] = __ldg(&x0[lane + i * 32]);
        xb[i] = __ldg(&x1[lane + i * 32]);
    }

    float n0 = 0.f, n1 = 0.f, xs0 = 0.f, xs1 = 0.f, ys = 0.f;
#pragma unroll
    for (int i = 0; i < 4; i++) {
        float4 y = yv[i], a = xa[i], c = xb[i];
        ys  += y.x * y.x + y.y * y.y + y.z * y.z + y.w * y.w;
        n0  += a.x * y.x + a.y * y.y + a.z * y.z + a.w * y.w;
        xs0 += a.x * a.x + a.y * a.y + a.z * a.z + a.w * a.w;
        n1  += c.x * y.x + c.y * y.y + c.z * y.z + c.w * y.w;
        xs1 += c.x * c.x + c.y * c.y + c.z * c.z + c.w * c.w;
    }
#pragma unroll
    for (int o = 16; o; o >>= 1) {
        n0  += __shfl_xor_sync(0xffffffffu, n0,  o);
        n1  += __shfl_xor_sync(0xffffffffu, n1,  o);
        xs0 += __shfl_xor_sync(0xffffffffu, xs0, o);
        xs1 += __shfl_xor_sync(0xffffffffu, xs1, o);
        ys  += __shfl_xor_sync(0xffffffffu, ys,  o);
    }
    if (lane < 2) {
        const int t = t0 + lane;
        float num = lane ? n1 : n0;
        float xn2 = lane ? xs1 : xs0;
        float xn  = fmaxf(sqrtf(xn2), 1e-8f);
        float yn  = fmaxf(sqrtf(ys),  1e-8f);
        float w   = num / (xn * yn);
        int tv    = targets[b * (T + 1) + t];
        bool msk  = (t == 0) || (tv > 0);
        g_w[b * T + t] = msk ? w : -1.0f;
    }
}

// ---------------------------------------------------------------------------
// Kernel 2 (fused): grid (NBLK, B), 512 threads. 32-bit key ranking with
// static index tie-break (warp-owned slice, LDS.128 broadcast, smem atomics).
// Gather (R9's validated 2-row loop) accumulates straight into g_total via
// float REDG atomics; the last-arriving block per b only normalizes.
// ---------------------------------------------------------------------------
__global__ __launch_bounds__(512) void k_fused(
    const int*   __restrict__ targets,  // (B, T+1) int32
    const float* __restrict__ attns,    // (L, B, H, T, S)
    float*       __restrict__ out)      // (B, S)
{
    __shared__ unsigned keys[T];             // 2 KB (mapped uint32)
    __shared__ float    wvals[T];            // 2 KB (raw weights)
    __shared__ int      rank[CHUNK];
    __shared__ int      sl[CHUNK];
    __shared__ float    slw[CHUNK];
    __shared__ int      s_last;
    __shared__ float    wmin[8], wmax[8];
    __shared__ float    s_mn, s_mx;

    const int c    = blockIdx.x;   // 0..NBLK-1
    const int b    = blockIdx.y;
    const int tid  = threadIdx.x;  // 0..511
    const int lane = tid & 31;
    const int warp = tid >> 5;

    // ---- Phase 1: keys + m
    if (tid < CHUNK) rank[tid] = 0;
    float w = g_w[b * T + tid];
    unsigned uf = __float_as_uint(w);
    uf = (uf & 0x80000000u) ? ~uf : (uf | 0x80000000u);   // order-preserving
    keys[tid]  = uf;
    wvals[tid] = w;

    int tv  = targets[b * (T + 1) + tid];
    int cnt = __syncthreads_count((tid == 0) || (tv > 0));
    int m   = (int)ceilf((float)cnt * 0.1f);
    m = m < K_TOP ? m : K_TOP;

    // ---- Phase 2: chunk-local rank. lane = t_local, warp = 32-key slice;
    // all lanes of a warp read the SAME uint4 (broadcast, conflict-free).
    // Predecessor test: (k > mk) || (k == mk && gidx < myt)  [jax stability]
    {
        const int myt = c * CHUNK + lane;
        const unsigned mk = keys[myt];
        const uint4* kp = reinterpret_cast<const uint4*>(keys + warp * 32);
        int r = 0;
#pragma unroll
        for (int i = 0; i < 8; i++) {
            uint4 kv = kp[i];
            const int gb = warp * 32 + i * 4;
            r += (kv.x > mk) || ((kv.x == mk) && (gb + 0 < myt));
            r += (kv.y > mk) || ((kv.y == mk) && (gb + 1 < myt));
            r += (kv.z > mk) || ((kv.z == mk) && (gb + 2 < myt));
            r += (kv.w > mk) || ((kv.w == mk) && (gb + 3 < myt));
        }
        atomicAdd(&rank[lane], r);     // 32 spread addrs per warp
    }
    __syncthreads();

    // ---- Phase 3: selected list for this chunk, t-order (deterministic)
    bool selme = (tid < CHUNK) && (rank[tid] < m);
    if (selme) {
        int pos = 0;
#pragma unroll
        for (int i = 0; i < CHUNK; i++) pos += (i < tid) && (rank[i] < m);
        sl[pos]  = tid;
        slw[pos] = wvals[c * CHUNK + tid];
    }
    int ns = __syncthreads_count(selme);

    // ---- Phase 4: gather (R9 loop) -> REDG accumulate into g_total
    const int jsub = tid / S;          // 0,1 active; tid >= 392 idle
    const int s    = tid - jsub * S;
    if (jsub < 2 && ns > 0) {
        const float* base = attns + ((size_t)(LAYER_ID * B + b)) * H * T * S + s;
        float acc = 0.f;
        for (int i = jsub; i < ns; i += 4) {   // handles i and i+2 per iter
            int i2 = i + 2;
            bool a2 = (i2 < ns);
            int   t0i = c * CHUNK + sl[i];
            int   t1i = a2 ? (c * CHUNK + sl[i2]) : t0i;
            float w0  = slw[i];
            float w1  = a2 ? slw[i2] : 0.f;
            const float* p0 = base + (size_t)t0i * S;
            const float* p1 = base + (size_t)t1i * S;
            float v0[8], v1[8];
#pragma unroll
            for (int h = 0; h < H; h++) {
                v0[h] = __ldg(p0 + (size_t)h * T * S);
                v1[h] = __ldg(p1 + (size_t)h * T * S);
            }
            float h0 = 0.f, h1 = 0.f;
#pragma unroll
            for (int h = 0; h < H; h++) { h0 += v0[h]; h1 += v1[h]; }
            acc += fmaxf(w0 * (h0 * 0.125f), 0.f);
            if (a2) acc += fmaxf(w1 * (h1 * 0.125f), 0.f);
        }
        atomicAdd(&g_total[b][s], acc);        // REDG, no return
    }

    // ---- Phase 5: arrival; last block per b normalizes (tiny tail)
    __threadfence();
    __syncthreads();
    if (tid == 0) {
        int done = atomicAdd(&g_sync[b], 1);
        s_last = (done == NBLK - 1);
    }
    __syncthreads();
    if (!s_last) return;
    if (tid == 0) g_sync[b] = 0;       // reset for next graph replay
    __threadfence();                   // acquire: all adds visible

    const bool active = (tid < S);
    float acc = 0.f;
    if (active) acc = g_total[b][tid] / (float)m;

    // warp-shuffle min/max over s (256 participating threads, 2 barriers)
    if (tid < 256) {
        float mn = active ? acc :  CUDART_INF_F;
        float mx = active ? acc : -CUDART_INF_F;
#pragma unroll
        for (int o = 16; o; o >>= 1) {
            mn = fminf(mn, __shfl_xor_sync(0xffffffffu, mn, o));
            mx = fmaxf(mx, __shfl_xor_sync(0xffffffffu, mx, o));
        }
        if (lane == 0) { wmin[warp] = mn; wmax[warp] = mx; }
    }
    __syncthreads();
    if (tid < 32) {
        float mn = (tid < 8) ? wmin[tid] :  CUDART_INF_F;
        float mx = (tid < 8) ? wmax[tid] : -CUDART_INF_F;
#pragma unroll
        for (int o = 4; o; o >>= 1) {
            mn = fminf(mn, __shfl_xor_sync(0xffffffffu, mn, o));
            mx = fmaxf(mx, __shfl_xor_sync(0xffffffffu, mx, o));
        }
        if (tid == 0) { s_mn = mn; s_mx = mx; }
    }
    __syncthreads();

    if (active)
        out[b * S + tid] = (acc - s_mn) / fmaxf(s_mx - s_mn, 1e-12f);
}

// ---------------------------------------------------------------------------
extern "C" void kernel_launch(void* const* d_in, const int* in_sizes, int n_in,
                              void* d_out, int out_size)
{
    const float* fore    = (const float*)d_in[0];  // (B, D)
    const float* embed   = (const float*)d_in[1];  // (B, T, D)
    const float* attns   = (const float*)d_in[2];  // (L, B, H, T, S)
    const int*   targets = (const int*)  d_in[3];  // (B, T+1) int32
    float* out = (float*)d_out;

    k_weights<<<dim3(T / 16, B), 256>>>(fore, embed, targets);
    k_fused<<<dim3(NBLK, B), 512>>>(targets, attns, out);
}